// round 4
// baseline (speedup 1.0000x reference)
#include <cuda_runtime.h>
#include <math.h>

#define N_CRIT  128
#define N_PAIRS 8128
#define N_TOT   (N_CRIT + N_PAIRS)   // 8256
#define N_VEC4  (N_TOT / 4)          // 2064
#define MIN_W   1e-7f
#define PREP_T  1024

// Effective (constrained) weight vector: [wc_eff (128) | wint_eff (8128)]
__device__ float g_w[N_TOT];
__device__ float g_inv_sum;
__device__ int   g_row_ctr;   // dynamic row dispenser, reset by prep each launch

// ---------------------------------------------------------------------------
// Prep: apply constraints, build contiguous weight vector, compute 1/sum,
// reset the row counter. One block of 1024 threads; pairs distributed flat,
// (i,j) recovered from the pair index by triangle inversion.
// ---------------------------------------------------------------------------
__global__ void __launch_bounds__(PREP_T)
choquet_prep_kernel(const float* __restrict__ wc,
                    const float* __restrict__ wint) {
    __shared__ float s_wc[N_CRIT];
    __shared__ float s_part[PREP_T / 32];
    const int t = threadIdx.x;

    if (t == 0) g_row_ctr = 0;

    if (t < N_CRIT) {
        float wce = wc[t];
        if (wce < 0.f) wce = MIN_W;
        s_wc[t] = wce;
        g_w[t]  = wce;
    }
    __syncthreads();

    float sum = (t < N_CRIT) ? s_wc[t] : 0.f;

    // Pair p -> (i, j): p = i*(2*N-1-i)/2 + (j-i-1)
    #pragma unroll
    for (int k = 0; k < (N_PAIRS + PREP_T - 1) / PREP_T; k++) {
        const int p = t + k * PREP_T;
        if (p < N_PAIRS) {
            const float disc = sqrtf((float)(65025 - 8 * p));
            int i = (int)((255.0f - disc) * 0.5f);
            int base = i * (2 * N_CRIT - 1 - i) / 2;
            if (base > p)                        { i--; base = i * (2 * N_CRIT - 1 - i) / 2; }
            else if (p - base >= N_CRIT - 1 - i) { i++; base = i * (2 * N_CRIT - 1 - i) / 2; }
            const int j = p - base + i + 1;
            const float lo = fmaxf(-s_wc[i], -s_wc[j]);
            const float v  = fmaxf(wint[p], lo);
            g_w[N_CRIT + p] = v;
            sum += v;
        }
    }

    #pragma unroll
    for (int off = 16; off > 0; off >>= 1)
        sum += __shfl_xor_sync(0xFFFFFFFFu, sum, off);
    if ((t & 31) == 0) s_part[t >> 5] = sum;
    __syncthreads();
    if (t < 32) {
        float v = (t < PREP_T / 32) ? s_part[t] : 0.f;
        #pragma unroll
        for (int off = 16; off > 0; off >>= 1)
            v += __shfl_xor_sync(0xFFFFFFFFu, v, off);
        if (t == 0) g_inv_sum = 1.0f / v;
    }
}

// ---------------------------------------------------------------------------
// GEMV: persistent warps, one row at a time grabbed from a global counter.
// Exactly one resident wave (grid = SMs * 8 blocks, 8 warps each), so
// occupancy stays pinned at max until the rows run out (no ragged 2nd wave).
// Inner loop identical to the proven R1 body (regs ~30).
// Epilogue: sigmoid(acc * inv_sum - thr).
// ---------------------------------------------------------------------------
__global__ void __launch_bounds__(256, 8)
choquet_gemv_kernel(const float* __restrict__ x,
                    const float* __restrict__ thr,
                    float* __restrict__ out,
                    int rows) {
    const int lane = threadIdx.x & 31;
    const float4* __restrict__ w4 = reinterpret_cast<const float4*>(g_w);

    while (true) {
        int r;
        if (lane == 0) r = atomicAdd(&g_row_ctr, 1);
        r = __shfl_sync(0xFFFFFFFFu, r, 0);
        if (r >= rows) break;

        const float4* __restrict__ xr = reinterpret_cast<const float4*>(
            x + (size_t)r * N_TOT);

        float acc = 0.f;
        // 2064 = 64*32 + 16
        #pragma unroll 4
        for (int i = lane; i < 2048; i += 32) {
            const float4 a = xr[i];
            const float4 b = w4[i];
            acc = fmaf(a.x, b.x, acc);
            acc = fmaf(a.y, b.y, acc);
            acc = fmaf(a.z, b.z, acc);
            acc = fmaf(a.w, b.w, acc);
        }
        if (lane < 16) {
            const int i = 2048 + lane;
            const float4 a = xr[i];
            const float4 b = w4[i];
            acc = fmaf(a.x, b.x, acc);
            acc = fmaf(a.y, b.y, acc);
            acc = fmaf(a.z, b.z, acc);
            acc = fmaf(a.w, b.w, acc);
        }

        #pragma unroll
        for (int off = 16; off > 0; off >>= 1)
            acc += __shfl_xor_sync(0xFFFFFFFFu, acc, off);

        if (lane == 0) {
            const float s = fmaf(acc, g_inv_sum, -thr[0]);
            out[r] = 1.0f / (1.0f + __expf(-s));
        }
    }
}

extern "C" void kernel_launch(void* const* d_in, const int* in_sizes, int n_in,
                              void* d_out, int out_size) {
    const float* x    = (const float*)d_in[0];
    const float* wc   = (const float*)d_in[1];
    const float* wint = (const float*)d_in[2];
    const float* thr  = (const float*)d_in[3];
    float* out = (float*)d_out;

    const int rows = in_sizes[0] / N_TOT;

    choquet_prep_kernel<<<1, PREP_T>>>(wc, wint);

    // One resident wave: 152 SMs (GB300) x 8 blocks/SM. Extra blocks on a
    // 148-SM part would just drain the counter; work stays balanced.
    choquet_gemv_kernel<<<152 * 8, 256>>>(x, thr, out, rows);
}

// round 5
// speedup vs baseline: 1.2014x; 1.2014x over previous
#include <cuda_runtime.h>
#include <math.h>

#define N_CRIT  128
#define N_PAIRS 8128
#define N_TOT   (N_CRIT + N_PAIRS)   // 8256
#define N_VEC4  (N_TOT / 4)          // 2064
#define MIN_W   1e-7f
#define PREP_T  1024

// Effective (constrained) weight vector: [wc_eff (128) | wint_eff (8128)]
__device__ float g_w[N_TOT];
__device__ float g_inv_sum;

// ---------------------------------------------------------------------------
// Prep (parallel, ~2us): apply constraints, build contiguous weight vector,
// compute 1/sum. One block of 1024 threads; pairs distributed flat, (i,j)
// recovered from the pair index by triangle inversion.
// ---------------------------------------------------------------------------
__global__ void __launch_bounds__(PREP_T)
choquet_prep_kernel(const float* __restrict__ wc,
                    const float* __restrict__ wint) {
    __shared__ float s_wc[N_CRIT];
    __shared__ float s_part[PREP_T / 32];
    const int t = threadIdx.x;

    if (t < N_CRIT) {
        float wce = wc[t];
        if (wce < 0.f) wce = MIN_W;
        s_wc[t] = wce;
        g_w[t]  = wce;
    }
    __syncthreads();

    float sum = (t < N_CRIT) ? s_wc[t] : 0.f;

    // Pair p -> (i, j): p = i*(2*N-1-i)/2 + (j-i-1)
    #pragma unroll
    for (int k = 0; k < (N_PAIRS + PREP_T - 1) / PREP_T; k++) {
        const int p = t + k * PREP_T;
        if (p < N_PAIRS) {
            const float disc = sqrtf((float)(65025 - 8 * p));
            int i = (int)((255.0f - disc) * 0.5f);
            int base = i * (2 * N_CRIT - 1 - i) / 2;
            if (base > p)                        { i--; base = i * (2 * N_CRIT - 1 - i) / 2; }
            else if (p - base >= N_CRIT - 1 - i) { i++; base = i * (2 * N_CRIT - 1 - i) / 2; }
            const int j = p - base + i + 1;
            const float lo = fmaxf(-s_wc[i], -s_wc[j]);
            const float v  = fmaxf(wint[p], lo);
            g_w[N_CRIT + p] = v;
            sum += v;
        }
    }

    #pragma unroll
    for (int off = 16; off > 0; off >>= 1)
        sum += __shfl_xor_sync(0xFFFFFFFFu, sum, off);
    if ((t & 31) == 0) s_part[t >> 5] = sum;
    __syncthreads();
    if (t < 32) {
        float v = (t < PREP_T / 32) ? s_part[t] : 0.f;
        #pragma unroll
        for (int off = 16; off > 0; off >>= 1)
            v += __shfl_xor_sync(0xFFFFFFFFu, v, off);
        if (t == 0) g_inv_sum = 1.0f / v;
    }
}

// ---------------------------------------------------------------------------
// GEMV: EXACT R1 body (measured best: 84.0us, DRAM 81.8%). One warp per row,
// 2064 float4 per row, plain loads, unroll 4, warp shuffle reduce.
// Epilogue: sigmoid(acc * inv_sum - thr).
// ---------------------------------------------------------------------------
__global__ void __launch_bounds__(256)
choquet_gemv_kernel(const float* __restrict__ x,
                    const float* __restrict__ thr,
                    float* __restrict__ out,
                    int rows) {
    const int warp = (blockIdx.x * blockDim.x + threadIdx.x) >> 5;
    const int lane = threadIdx.x & 31;
    if (warp >= rows) return;

    const float4* __restrict__ xr = reinterpret_cast<const float4*>(
        x + (size_t)warp * N_TOT);
    const float4* __restrict__ w4 = reinterpret_cast<const float4*>(g_w);

    float acc = 0.f;
    // N_VEC4 = 2064 = 64*32 + 16: main unrolled loop covers 64 iters/lane,
    // the tail covers lanes < 16.
    #pragma unroll 4
    for (int i = lane; i < 2048; i += 32) {
        const float4 a = xr[i];
        const float4 b = w4[i];
        acc = fmaf(a.x, b.x, acc);
        acc = fmaf(a.y, b.y, acc);
        acc = fmaf(a.z, b.z, acc);
        acc = fmaf(a.w, b.w, acc);
    }
    {
        const int i = 2048 + lane;
        if (i < N_VEC4) {
            const float4 a = xr[i];
            const float4 b = w4[i];
            acc = fmaf(a.x, b.x, acc);
            acc = fmaf(a.y, b.y, acc);
            acc = fmaf(a.z, b.z, acc);
            acc = fmaf(a.w, b.w, acc);
        }
    }

    // Warp reduction
    #pragma unroll
    for (int off = 16; off > 0; off >>= 1)
        acc += __shfl_xor_sync(0xFFFFFFFFu, acc, off);

    if (lane == 0) {
        const float s = fmaf(acc, g_inv_sum, -thr[0]);
        out[warp] = 1.0f / (1.0f + __expf(-s));
    }
}

extern "C" void kernel_launch(void* const* d_in, const int* in_sizes, int n_in,
                              void* d_out, int out_size) {
    const float* x    = (const float*)d_in[0];
    const float* wc   = (const float*)d_in[1];
    const float* wint = (const float*)d_in[2];
    const float* thr  = (const float*)d_in[3];
    float* out = (float*)d_out;

    const int rows = in_sizes[0] / N_TOT;

    choquet_prep_kernel<<<1, PREP_T>>>(wc, wint);

    const int threads = 256;                 // 8 warps/block -> 8 rows/block
    const int blocks  = (rows + 7) / 8;
    choquet_gemv_kernel<<<blocks, threads>>>(x, thr, out, rows);
}

// round 6
// speedup vs baseline: 1.2062x; 1.0040x over previous
#include <cuda_runtime.h>
#include <math.h>

#define N_CRIT  128
#define N_PAIRS 8128
#define N_TOT   (N_CRIT + N_PAIRS)   // 8256
#define N_VEC4  (N_TOT / 4)          // 2064
#define QTR     (N_VEC4 / 4)         // 516 float4 per quarter-row
#define MIN_W   1e-7f
#define PREP_T  1024

// Effective (constrained) weight vector: [wc_eff (128) | wint_eff (8128)]
__device__ float g_w[N_TOT];
__device__ float g_inv_sum;

// ---------------------------------------------------------------------------
// Prep (parallel, ~2us): apply constraints, build contiguous weight vector,
// compute 1/sum. One block of 1024 threads; pairs distributed flat, (i,j)
// recovered from the pair index by triangle inversion.
// ---------------------------------------------------------------------------
__global__ void __launch_bounds__(PREP_T)
choquet_prep_kernel(const float* __restrict__ wc,
                    const float* __restrict__ wint) {
    __shared__ float s_wc[N_CRIT];
    __shared__ float s_part[PREP_T / 32];
    const int t = threadIdx.x;

    if (t < N_CRIT) {
        float wce = wc[t];
        if (wce < 0.f) wce = MIN_W;
        s_wc[t] = wce;
        g_w[t]  = wce;
    }
    __syncthreads();

    float sum = (t < N_CRIT) ? s_wc[t] : 0.f;

    // Pair p -> (i, j): p = i*(2*N-1-i)/2 + (j-i-1)
    #pragma unroll
    for (int k = 0; k < (N_PAIRS + PREP_T - 1) / PREP_T; k++) {
        const int p = t + k * PREP_T;
        if (p < N_PAIRS) {
            const float disc = sqrtf((float)(65025 - 8 * p));
            int i = (int)((255.0f - disc) * 0.5f);
            int base = i * (2 * N_CRIT - 1 - i) / 2;
            if (base > p)                        { i--; base = i * (2 * N_CRIT - 1 - i) / 2; }
            else if (p - base >= N_CRIT - 1 - i) { i++; base = i * (2 * N_CRIT - 1 - i) / 2; }
            const int j = p - base + i + 1;
            const float lo = fmaxf(-s_wc[i], -s_wc[j]);
            const float v  = fmaxf(wint[p], lo);
            g_w[N_CRIT + p] = v;
            sum += v;
        }
    }

    #pragma unroll
    for (int off = 16; off > 0; off >>= 1)
        sum += __shfl_xor_sync(0xFFFFFFFFu, sum, off);
    if ((t & 31) == 0) s_part[t >> 5] = sum;
    __syncthreads();
    if (t < 32) {
        float v = (t < PREP_T / 32) ? s_part[t] : 0.f;
        #pragma unroll
        for (int off = 16; off > 0; off >>= 1)
            v += __shfl_xor_sync(0xFFFFFFFFu, v, off);
        if (t == 0) g_inv_sum = 1.0f / v;
    }
}

// ---------------------------------------------------------------------------
// GEMV: quarter-row work units, fully static. One block = 2 rows; each of the
// 8 warps owns one quarter-row (516 float4), same strided float4 inner loop
// as the proven R1 body. smem reduce across the 4 warps of each row.
// Grid = rows/2 = 8192 blocks -> ~6.7 waves, tail quantization ~4%.
// Epilogue: sigmoid(acc * inv_sum - thr).
// ---------------------------------------------------------------------------
__global__ void __launch_bounds__(256, 8)
choquet_gemv_kernel(const float* __restrict__ x,
                    const float* __restrict__ thr,
                    float* __restrict__ out,
                    int rows) {
    __shared__ float s_part[8];

    const int warp = threadIdx.x >> 5;     // 0..7
    const int lane = threadIdx.x & 31;
    const int rloc = warp >> 2;             // 0 or 1: which row of this block
    const int q    = warp & 3;              // quarter index within the row

    const int r = blockIdx.x * 2 + rloc;
    // Guard (rows is even in practice): alias out-of-range row to row 0;
    // its result is never stored.
    const int rr = (r < rows) ? r : 0;

    const float4* __restrict__ xr = reinterpret_cast<const float4*>(
        x + (size_t)rr * N_TOT);
    const float4* __restrict__ w4 = reinterpret_cast<const float4*>(g_w);

    const int base = q * QTR;               // 0, 516, 1032, 1548

    float acc = 0.f;
    // QTR = 516 = 16*32 + 4
    #pragma unroll 4
    for (int k = 0; k < 16; k++) {
        const int i = base + k * 32 + lane;
        const float4 a = xr[i];
        const float4 b = w4[i];
        acc = fmaf(a.x, b.x, acc);
        acc = fmaf(a.y, b.y, acc);
        acc = fmaf(a.z, b.z, acc);
        acc = fmaf(a.w, b.w, acc);
    }
    if (lane < 4) {
        const int i = base + 512 + lane;
        const float4 a = xr[i];
        const float4 b = w4[i];
        acc = fmaf(a.x, b.x, acc);
        acc = fmaf(a.y, b.y, acc);
        acc = fmaf(a.z, b.z, acc);
        acc = fmaf(a.w, b.w, acc);
    }

    // Warp reduction
    #pragma unroll
    for (int off = 16; off > 0; off >>= 1)
        acc += __shfl_xor_sync(0xFFFFFFFFu, acc, off);
    if (lane == 0) s_part[warp] = acc;
    __syncthreads();

    // Threads 0 and 1 finalize the block's two rows
    if (threadIdx.x < 2) {
        const int ro = blockIdx.x * 2 + threadIdx.x;
        if (ro < rows) {
            const int b4 = threadIdx.x * 4;
            const float tot = (s_part[b4] + s_part[b4 + 1])
                            + (s_part[b4 + 2] + s_part[b4 + 3]);
            const float s = fmaf(tot, g_inv_sum, -thr[0]);
            out[ro] = 1.0f / (1.0f + __expf(-s));
        }
    }
}

extern "C" void kernel_launch(void* const* d_in, const int* in_sizes, int n_in,
                              void* d_out, int out_size) {
    const float* x    = (const float*)d_in[0];
    const float* wc   = (const float*)d_in[1];
    const float* wint = (const float*)d_in[2];
    const float* thr  = (const float*)d_in[3];
    float* out = (float*)d_out;

    const int rows = in_sizes[0] / N_TOT;

    choquet_prep_kernel<<<1, PREP_T>>>(wc, wint);

    const int blocks = (rows + 1) / 2;       // 2 rows per block
    choquet_gemv_kernel<<<blocks, 256>>>(x, thr, out, rows);
}